// round 6
// baseline (speedup 1.0000x reference)
#include <cuda_runtime.h>
#include <cuda_bf16.h>
#include <cstdint>

#define N_IMG 128
#define N_REG 36
#define N_CAP 128
#define N_WORD 32
#define DIM 1024
#define M_TOT (N_IMG * N_REG)   // 4608
#define N_TOT (N_CAP * N_WORD)  // 4096

// ---------------- scratch (device globals, no runtime alloc) ----------------
__device__ float g_raw[N_CAP * N_IMG * N_REG * N_WORD];   // 75.5 MB
__device__ float g_G[N_IMG * N_REG * N_REG];
__device__ float g_H[N_CAP * N_WORD * N_WORD];
__device__ __nv_bfloat16 g_Ah[M_TOT * DIM], g_Al[M_TOT * DIM];
__device__ __nv_bfloat16 g_Bh[N_TOT * DIM], g_Bl[N_TOT * DIM];

__device__ __forceinline__ float lrelu(float x) { return fmaxf(x, 0.1f * x); }

__device__ __forceinline__ uint32_t smem_u32(const void* p) {
    uint32_t a;
    asm("{ .reg .u64 t; cvta.to.shared.u64 t, %1; cvt.u32.u64 %0, t; }" : "=r"(a) : "l"(p));
    return a;
}
__device__ __forceinline__ void ldsm4(uint32_t* r, uint32_t addr) {
    asm volatile("ldmatrix.sync.aligned.m8n8.x4.shared.b16 {%0,%1,%2,%3}, [%4];"
                 : "=r"(r[0]), "=r"(r[1]), "=r"(r[2]), "=r"(r[3]) : "r"(addr));
}
__device__ __forceinline__ void mma16816(float* d, const uint32_t* a, const uint32_t* b) {
    asm volatile(
        "mma.sync.aligned.m16n8k16.row.col.f32.bf16.bf16.f32 "
        "{%0,%1,%2,%3}, {%4,%5,%6,%7}, {%8,%9}, {%0,%1,%2,%3};"
        : "+f"(d[0]), "+f"(d[1]), "+f"(d[2]), "+f"(d[3])
        : "r"(a[0]), "r"(a[1]), "r"(a[2]), "r"(a[3]), "r"(b[0]), "r"(b[1]));
}
__device__ __forceinline__ void cpa16(uint32_t saddr, const void* gaddr) {
    asm volatile("cp.async.cg.shared.global [%0], [%1], 16;" :: "r"(saddr), "l"(gaddr));
}
#define CPA_COMMIT() asm volatile("cp.async.commit_group;" ::: "memory")
#define CPA_WAIT(n)  asm volatile("cp.async.wait_group %0;" :: "n"(n) : "memory")

// ---------------------------------------------------------------------------
// K0: split fp32 -> bf16 hi/lo
// ---------------------------------------------------------------------------
__global__ __launch_bounds__(256) void k_split(const float* __restrict__ src,
                                               __nv_bfloat16* __restrict__ hi,
                                               __nv_bfloat16* __restrict__ lo, int n4) {
    int idx = blockIdx.x * 256 + threadIdx.x;
    if (idx >= n4) return;
    float4 v = ((const float4*)src)[idx];
    __nv_bfloat16 h0 = __float2bfloat16(v.x), h1 = __float2bfloat16(v.y);
    __nv_bfloat16 h2 = __float2bfloat16(v.z), h3 = __float2bfloat16(v.w);
    __nv_bfloat162* H = (__nv_bfloat162*)hi;
    __nv_bfloat162* L = (__nv_bfloat162*)lo;
    H[2 * idx] = __nv_bfloat162(h0, h1);
    H[2 * idx + 1] = __nv_bfloat162(h2, h3);
    L[2 * idx] = __nv_bfloat162(__float2bfloat16(v.x - __bfloat162float(h0)),
                                __float2bfloat16(v.y - __bfloat162float(h1)));
    L[2 * idx + 1] = __nv_bfloat162(__float2bfloat16(v.z - __bfloat162float(h2)),
                                    __float2bfloat16(v.w - __bfloat162float(h3)));
}

// ---------------------------------------------------------------------------
// K1/K2: Gram matrices
// ---------------------------------------------------------------------------
__global__ __launch_bounds__(256) void k_gram_img(const float* __restrict__ imgs) {
    __shared__ float s[N_REG * 132];
    int i = blockIdx.x, tid = threadIdx.x;
    float acc[6];
#pragma unroll
    for (int j = 0; j < 6; j++) acc[j] = 0.f;
    const float* base = imgs + (size_t)i * N_REG * DIM;
    for (int k0 = 0; k0 < DIM; k0 += 128) {
        for (int idx = tid; idx < N_REG * 128; idx += 256) {
            int r = idx >> 7, k = idx & 127;
            s[r * 132 + k] = base[r * DIM + k0 + k];
        }
        __syncthreads();
#pragma unroll
        for (int j = 0; j < 6; j++) {
            int e = tid + 256 * j;
            if (e < N_REG * N_REG) {
                int r1 = e / N_REG, r2 = e - r1 * N_REG;
                const float4* pa = (const float4*)(s + r1 * 132);
                const float4* pb = (const float4*)(s + r2 * 132);
                float t = 0.f;
#pragma unroll
                for (int q = 0; q < 32; q++) {
                    float4 a = pa[q], b = pb[q];
                    t += a.x * b.x + a.y * b.y + a.z * b.z + a.w * b.w;
                }
                acc[j] += t;
            }
        }
        __syncthreads();
    }
#pragma unroll
    for (int j = 0; j < 6; j++) {
        int e = tid + 256 * j;
        if (e < N_REG * N_REG) g_G[i * N_REG * N_REG + e] = acc[j];
    }
}

__global__ __launch_bounds__(256) void k_gram_cap(const float* __restrict__ caps) {
    __shared__ float s[N_WORD * 132];
    int c = blockIdx.x, tid = threadIdx.x;
    float acc[4] = {0.f, 0.f, 0.f, 0.f};
    const float* base = caps + (size_t)c * N_WORD * DIM;
    for (int k0 = 0; k0 < DIM; k0 += 128) {
        for (int idx = tid; idx < N_WORD * 128; idx += 256) {
            int r = idx >> 7, k = idx & 127;
            s[r * 132 + k] = base[r * DIM + k0 + k];
        }
        __syncthreads();
#pragma unroll
        for (int j = 0; j < 4; j++) {
            int e = tid + 256 * j;
            int r1 = e >> 5, r2 = e & 31;
            const float4* pa = (const float4*)(s + r1 * 132);
            const float4* pb = (const float4*)(s + r2 * 132);
            float t = 0.f;
#pragma unroll
            for (int q = 0; q < 32; q++) {
                float4 a = pa[q], b = pb[q];
                t += a.x * b.x + a.y * b.y + a.z * b.z + a.w * b.w;
            }
            acc[j] += t;
        }
        __syncthreads();
    }
#pragma unroll
    for (int j = 0; j < 4; j++) g_H[c * 1024 + tid + 256 * j] = acc[j];
}

// ---------------------------------------------------------------------------
// K3: HMMA (mma.sync bf16) 3-split GEMM: raw = Ah.Bh^T + Ah.Bl^T + Al.Bh^T
// Tile 128x128, BK=16, 8 warps (2m x 4n), warp tile 64x32.
// smem rows: 16 bf16 payload @ 48B stride (rows hit distinct 16B segments
// mod 128 -> conflict-free ldmatrix).  cp.async double buffering.
// ---------------------------------------------------------------------------
#define TILE_B 6144              // 128 rows * 48 B
#define STAGE_B (4 * TILE_B)     // Ah, Al, Bh, Bl
#define SMEM_GEMM (2 * STAGE_B)  // 49152 B
#define NSTAGE 64                // 1024 / 16

__global__ __launch_bounds__(256) void k_gemm_hmma() {
    extern __shared__ char sm[];
    const uint32_t sb = smem_u32(sm);
    const int tid = threadIdx.x, wid = tid >> 5, lane = tid & 31;
    const int m0 = blockIdx.y * 128, n0 = blockIdx.x * 128;
    const int warp_m = wid >> 2, warp_n = wid & 3;

    // per-thread cp.async slot: row = tid>>1, half = tid&1 (per tile)
    const int ldrow = tid >> 1, ldhalf = tid & 1;
    const uint32_t s_off = ldrow * 48 + ldhalf * 16;
    const __nv_bfloat16* gp[4] = {
        g_Ah + (size_t)m0 * DIM, g_Al + (size_t)m0 * DIM,
        g_Bh + (size_t)n0 * DIM, g_Bl + (size_t)n0 * DIM};

    // ldmatrix lane addresses (byte offsets within a tile)
    const uint32_t a_off = (warp_m * 64 + (lane & 15)) * 48 + (lane >> 4) * 16;
    const uint32_t b_off = (warp_n * 32 + (lane & 7) + ((lane >> 4) << 3)) * 48 +
                           ((lane >> 3) & 1) * 16;

    float d[4][4][4];
#pragma unroll
    for (int mi = 0; mi < 4; mi++)
#pragma unroll
        for (int nj = 0; nj < 4; nj++)
#pragma unroll
            for (int e = 0; e < 4; e++) d[mi][nj][e] = 0.f;

    // prologue: stage 0
#pragma unroll
    for (int t = 0; t < 4; t++)
        cpa16(sb + t * TILE_B + s_off, gp[t] + (size_t)ldrow * DIM + ldhalf * 8);
    CPA_COMMIT();

    for (int j = 0; j < NSTAGE; j++) {
        if (j + 1 < NSTAGE) {
            uint32_t bs = ((j + 1) & 1) * STAGE_B;
#pragma unroll
            for (int t = 0; t < 4; t++)
                cpa16(sb + bs + t * TILE_B + s_off,
                      gp[t] + (size_t)ldrow * DIM + (j + 1) * 16 + ldhalf * 8);
            CPA_COMMIT();
            CPA_WAIT(1);
        } else {
            CPA_WAIT(0);
        }
        __syncthreads();

        const uint32_t bs = sb + (j & 1) * STAGE_B;
        uint32_t ah[4][4], al[4][4], bh[2][4], bl[2][4];
#pragma unroll
        for (int mi = 0; mi < 4; mi++) {
            ldsm4(ah[mi], bs + 0 * TILE_B + a_off + mi * 768);
            ldsm4(al[mi], bs + 1 * TILE_B + a_off + mi * 768);
        }
#pragma unroll
        for (int ni = 0; ni < 2; ni++) {
            ldsm4(bh[ni], bs + 2 * TILE_B + b_off + ni * 768);
            ldsm4(bl[ni], bs + 3 * TILE_B + b_off + ni * 768);
        }
#pragma unroll
        for (int mi = 0; mi < 4; mi++)
#pragma unroll
            for (int nj = 0; nj < 4; nj++) {
                const int ni = nj >> 1, pr = (nj & 1) * 2;
                mma16816(d[mi][nj], ah[mi], &bh[ni][pr]);
                mma16816(d[mi][nj], ah[mi], &bl[ni][pr]);
                mma16816(d[mi][nj], al[mi], &bh[ni][pr]);
            }
        __syncthreads();
    }

    // epilogue: scatter to raw[c][i][r][w]; warp n-range = one caption
    const int g = lane >> 2, tc = lane & 3;
    const int cidx = (n0 + warp_n * 32) >> 5;
    float* craw = g_raw + (size_t)cidx * (N_IMG * N_REG * N_WORD);
#pragma unroll
    for (int mi = 0; mi < 4; mi++) {
#pragma unroll
        for (int h = 0; h < 2; h++) {
            int m = m0 + warp_m * 64 + mi * 16 + g + h * 8;
            int gi = m / N_REG, gr = m - gi * N_REG;
            float* row = craw + ((size_t)gi * N_REG + gr) * N_WORD;
#pragma unroll
            for (int nj = 0; nj < 4; nj++) {
                int w = nj * 8 + tc * 2;
                *(float2*)(row + w) = make_float2(d[mi][nj][2 * h], d[mi][nj][2 * h + 1]);
            }
        }
    }
}

// ---------------------------------------------------------------------------
// K4: per-(i,c) focal attention + cosine.  64 threads:
//   warp0 -> 32 t2i word queries; warp1 -> 36 i2t region queries (lanes 28-31
//   take a second region).  Reciprocal norms; no max pass (args in [-2, 20]);
//   split accumulators; shuffle reductions.
// ---------------------------------------------------------------------------
__device__ __forceinline__ float i2t_cos(const float* sraw, const float* sH,
                                         const float* icn, const float* sG, int r) {
    const float* rw = sraw + r * 33;
    float a[N_WORD];
    float s0 = 0.f, s1 = 0.f;
#pragma unroll
    for (int w = 0; w < N_WORD; w++) {
        float e = __expf(20.f * lrelu(rw[w]) * icn[w]);
        a[w] = e;
        if (w & 1) s1 += e; else s0 += e;
    }
    float inv = 1.f / (s0 + s1);
    float u0 = 0.f, u1 = 0.f;
#pragma unroll
    for (int w = 0; w < N_WORD; w++) {
        a[w] *= inv;
        if (w & 1) u1 += a[w]; else u0 += a[w];
    }
    float suma = u0 + u1;
    float t0 = 0.f, t1 = 0.f;
#pragma unroll
    for (int w = 0; w < N_WORD; w++) {
        float t = (a[w] * (float)N_WORD - suma > 0.f) ? a[w] : 0.f;
        a[w] = t;
        if (w & 1) t1 += t; else t0 += t;
    }
    float ist = 1.f / (t0 + t1);
    float n0 = 0.f, n1 = 0.f;
#pragma unroll
    for (int w = 0; w < N_WORD; w++) {
        a[w] *= ist;
        if (w & 1) n1 += a[w] * rw[w]; else n0 += a[w] * rw[w];
    }
    float num = n0 + n1;
    float d2a = 0.f, d2b = 0.f;
#pragma unroll
    for (int w = 0; w < N_WORD; w++) {
        const float4* h4 = (const float4*)(sH + w * N_WORD);
        float q0 = 0.f, q1 = 0.f;
#pragma unroll
        for (int jj = 0; jj < 8; jj++) {
            float4 v = h4[jj];
            float p = v.x * a[4 * jj] + v.y * a[4 * jj + 1] + v.z * a[4 * jj + 2] + v.w * a[4 * jj + 3];
            if (jj & 1) q1 += p; else q0 += p;
        }
        if (w & 1) d2b += a[w] * (q0 + q1); else d2a += a[w] * (q0 + q1);
    }
    float imgn = fmaxf(sqrtf(sG[r * N_REG + r]), 1e-8f);
    float wn = fmaxf(sqrtf(fmaxf(d2a + d2b, 0.f)), 1e-8f);
    return num / (imgn * wn);
}

__global__ __launch_bounds__(64) void k_attn(float* __restrict__ out) {
    const int i = blockIdx.x, c = blockIdx.y;
    const int tid = threadIdx.x, lane = tid & 31;

    __shared__ float sraw[N_REG * 33];
    __shared__ float sG[N_REG * N_REG];
    __shared__ float sH[N_WORD * N_WORD];
    __shared__ float irn[N_REG], icn[N_WORD];
    __shared__ float redT, redI;

    const float* praw = g_raw + (size_t)(c * N_IMG + i) * (N_REG * N_WORD);
    for (int idx = tid; idx < N_REG * N_WORD; idx += 64)
        sraw[(idx >> 5) * 33 + (idx & 31)] = praw[idx];
    const float* pG = g_G + i * (N_REG * N_REG);
    for (int idx = tid; idx < N_REG * N_REG; idx += 64) sG[idx] = pG[idx];
    const float* pH = g_H + c * (N_WORD * N_WORD);
    for (int idx = tid; idx < N_WORD * N_WORD; idx += 64) sH[idx] = pH[idx];
    __syncthreads();

    if (tid < 32) {             // reciprocal row norms (t2i), rows 0-31
        float s0 = 0.f, s1 = 0.f;
#pragma unroll
        for (int w = 0; w < N_WORD; w++) {
            float x = lrelu(sraw[tid * 33 + w]);
            if (w & 1) s1 += x * x; else s0 += x * x;
        }
        irn[tid] = 1.f / (sqrtf(s0 + s1) + 1e-8f);
    } else {                    // reciprocal col norms (i2t) + rows 32-35
        int col = tid - 32;
        float s0 = 0.f, s1 = 0.f;
#pragma unroll
        for (int r = 0; r < N_REG; r++) {
            float x = lrelu(sraw[r * 33 + col]);
            if (r & 1) s1 += x * x; else s0 += x * x;
        }
        icn[col] = 1.f / (sqrtf(s0 + s1) + 1e-8f);
        if (col < 4) {
            int rr = 32 + col;
            float t0 = 0.f, t1 = 0.f;
#pragma unroll
            for (int w = 0; w < N_WORD; w++) {
                float x = lrelu(sraw[rr * 33 + w]);
                if (w & 1) t1 += x * x; else t0 += x * x;
            }
            irn[rr] = 1.f / (sqrtf(t0 + t1) + 1e-8f);
        }
    }
    __syncthreads();

    if (tid < 32) {
        // -------- t2i: query = word w = tid --------
        const int w = tid;
        float a[N_REG];
        float s0 = 0.f, s1 = 0.f;
#pragma unroll
        for (int r = 0; r < N_REG; r++) {
            float e = __expf(20.f * lrelu(sraw[r * 33 + w]) * irn[r]);
            a[r] = e;
            if (r & 1) s1 += e; else s0 += e;
        }
        float inv = 1.f / (s0 + s1);
        float u0 = 0.f, u1 = 0.f;
#pragma unroll
        for (int r = 0; r < N_REG; r++) {
            a[r] *= inv;
            if (r & 1) u1 += a[r]; else u0 += a[r];
        }
        float suma = u0 + u1;
        float t0 = 0.f, t1 = 0.f;
#pragma unroll
        for (int r = 0; r < N_REG; r++) {
            float t = (a[r] * (float)N_REG - suma > 0.f) ? a[r] : 0.f;
            a[r] = t;
            if (r & 1) t1 += t; else t0 += t;
        }
        float ist = 1.f / (t0 + t1);
        float m0 = 0.f, m1 = 0.f;
#pragma unroll
        for (int r = 0; r < N_REG; r++) {
            a[r] *= ist;
            if (r & 1) m1 += a[r] * sraw[r * 33 + w]; else m0 += a[r] * sraw[r * 33 + w];
        }
        float num = m0 + m1;
        float d2a = 0.f, d2b = 0.f;
#pragma unroll
        for (int r = 0; r < N_REG; r++) {
            const float4* g4 = (const float4*)(sG + r * N_REG);
            float q0 = 0.f, q1 = 0.f;
#pragma unroll
            for (int jj = 0; jj < 9; jj++) {
                float4 v = g4[jj];
                float p = v.x * a[4 * jj] + v.y * a[4 * jj + 1] + v.z * a[4 * jj + 2] + v.w * a[4 * jj + 3];
                if (jj & 1) q1 += p; else q0 += p;
            }
            if (r & 1) d2b += a[r] * (q0 + q1); else d2a += a[r] * (q0 + q1);
        }
        float capn = fmaxf(sqrtf(sH[w * N_WORD + w]), 1e-8f);
        float wn = fmaxf(sqrtf(fmaxf(d2a + d2b, 0.f)), 1e-8f);
        float v = num / (capn * wn);
#pragma unroll
        for (int off = 16; off; off >>= 1) v += __shfl_xor_sync(0xffffffffu, v, off);
        if (lane == 0) redT = v;
    } else {
        float v = i2t_cos(sraw, sH, icn, sG, lane);
        if (lane >= 28) v += i2t_cos(sraw, sH, icn, sG, lane + 4);
#pragma unroll
        for (int off = 16; off; off >>= 1) v += __shfl_xor_sync(0xffffffffu, v, off);
        if (lane == 0) redI = v;
    }
    __syncthreads();
    if (tid == 0)
        out[i * N_CAP + c] = redT * (1.f / N_WORD) + redI * (1.f / N_REG);
}

// ---------------------------------------------------------------------------
extern "C" void kernel_launch(void* const* d_in, const int* in_sizes, int n_in,
                              void* d_out, int out_size) {
    const float* images = (const float*)d_in[0];     // (128, 36, 1024)
    const float* captions = (const float*)d_in[1];   // (128, 32, 1024)
    float* out = (float*)d_out;                      // (128, 128)

    cudaFuncSetAttribute(k_gemm_hmma, cudaFuncAttributeMaxDynamicSharedMemorySize, SMEM_GEMM);

    __nv_bfloat16 *Ah, *Al, *Bh, *Bl;
    cudaGetSymbolAddress((void**)&Ah, g_Ah);
    cudaGetSymbolAddress((void**)&Al, g_Al);
    cudaGetSymbolAddress((void**)&Bh, g_Bh);
    cudaGetSymbolAddress((void**)&Bl, g_Bl);

    k_split<<<(M_TOT * DIM / 4 + 255) / 256, 256>>>(images, Ah, Al, M_TOT * DIM / 4);
    k_split<<<(N_TOT * DIM / 4 + 255) / 256, 256>>>(captions, Bh, Bl, N_TOT * DIM / 4);
    k_gram_img<<<N_IMG, 256>>>(images);
    k_gram_cap<<<N_CAP, 256>>>(captions);
    k_gemm_hmma<<<dim3(N_TOT / 128, M_TOT / 128), 256, SMEM_GEMM>>>();
    k_attn<<<dim3(N_IMG, N_CAP), 64>>>(out);
}